// round 4
// baseline (speedup 1.0000x reference)
#include <cuda_runtime.h>
#include <math.h>

#define BB 16
#define SS 512
#define DD 512
#define VV 32000
#define KK 4
#define TT 64
#define NR (BB*KK)     // 64 rows
#define NCG (VV/256)   // 125 vocab col-groups of 256
#define SOS_TOK 1
#define EOS_TOK 2
#define PAD_TOK 0
#define NEGV (-1e9f)

// ---------------- device state ----------------
__device__ float g_encKT[BB*DD*SS];    // [b][e][s]
__device__ float g_hT[DD*NR];          // [d][row]
__device__ float g_q[NR*DD];           // q per row
__device__ float g_pmax[NR*NCG];
__device__ float g_psum[NR*NCG];
__device__ float g_pval[NR*NCG*4];
__device__ int   g_pidx[NR*NCG*4];
__device__ int   g_tok[NR];
__device__ float g_scores[NR];
__device__ int   g_finished[NR];
__device__ int   g_seqs[BB*KK*TT];

__device__ __forceinline__ bool better(float xv, int xi, float yv, int yi) {
    return (xv > yv) || (xv == yv && xi < yi);
}

#define FMA2(acc,a,b) asm("fma.rn.f32x2 %0, %1, %2, %3;" : "=l"(acc) : "l"(a), "l"(b), "l"(acc))
#define PACK2(d,x,y)  asm("mov.b64 %0, {%1, %2};" : "=l"(d) : "f"(x), "f"(y))
#define UNPACK2(x,y,d) asm("mov.b64 {%0, %1}, %2;" : "=f"(x), "=f"(y) : "l"(d))

__device__ __forceinline__ void merge4(float av[4], int ai[4], const float bv[4], const int bi[4]) {
    float ov[4]; int oi[4]; int i = 0, j = 0;
    #pragma unroll
    for (int o = 0; o < 4; ++o) {
        bool ta = (j >= 4) || (i < 4 && better(av[i], ai[i], bv[j], bi[j]));
        if (ta) { ov[o] = av[i]; oi[o] = ai[i]; ++i; }
        else    { ov[o] = bv[j]; oi[o] = bi[j]; ++j; }
    }
    #pragma unroll
    for (int o = 0; o < 4; ++o) { av[o] = ov[o]; ai[o] = oi[o]; }
}

__device__ __forceinline__ void insert4(float av[4], int ai[4], float x, int xi) {
    if (better(x, xi, av[3], ai[3])) {
        if (better(x, xi, av[0], ai[0]))      { av[3]=av[2];ai[3]=ai[2]; av[2]=av[1];ai[2]=ai[1]; av[1]=av[0];ai[1]=ai[0]; av[0]=x;ai[0]=xi; }
        else if (better(x, xi, av[1], ai[1])) { av[3]=av[2];ai[3]=ai[2]; av[2]=av[1];ai[2]=ai[1]; av[1]=x;ai[1]=xi; }
        else if (better(x, xi, av[2], ai[2])) { av[3]=av[2];ai[3]=ai[2]; av[2]=x;ai[2]=xi; }
        else                                  { av[3]=x;ai[3]=xi; }
    }
}

// ---------------- kernel 0: tiled SGEMM  encKT[b][e][s] = enc[b,s,:] @ Wk ----------------
// grid (4, 64): x = 128-col e-tile, y: b = y>>2, s0 = (y&3)*128. 256 threads, 8x8 micro-tile.
__global__ void __launch_bounds__(256) enck_kernel(const float* __restrict__ enc,
                                                   const float* __restrict__ Wk) {
    __shared__ float As[32][132];   // [k][s]
    __shared__ float Bs[32][132];   // [k][e]
    int e0 = blockIdx.x * 128;
    int sy = blockIdx.y;
    int b = sy >> 2;
    int s0 = (sy & 3) * 128;
    int t = threadIdx.x;
    int tx = t & 15, ty = t >> 4;
    float acc[8][8];
    #pragma unroll
    for (int i = 0; i < 8; ++i)
        #pragma unroll
        for (int j = 0; j < 8; ++j) acc[i][j] = 0.f;

    for (int k0 = 0; k0 < 512; k0 += 32) {
        #pragma unroll
        for (int i = 0; i < 4; ++i) {
            int idx = t + i*256;
            int si = idx >> 3, kq = idx & 7;
            float4 f = *(const float4*)(enc + (size_t)(b*512 + s0 + si)*512 + k0 + kq*4);
            As[kq*4+0][si] = f.x; As[kq*4+1][si] = f.y; As[kq*4+2][si] = f.z; As[kq*4+3][si] = f.w;
        }
        #pragma unroll
        for (int i = 0; i < 4; ++i) {
            int idx = t + i*256;
            int kk = idx >> 5, eq = idx & 31;
            *(float4*)(&Bs[kk][eq*4]) = *(const float4*)(Wk + (size_t)(k0+kk)*512 + e0 + eq*4);
        }
        __syncthreads();
        #pragma unroll 4
        for (int kk = 0; kk < 32; ++kk) {
            float a[8], w[8];
            *(float4*)(a)   = *(const float4*)(&As[kk][ty*8]);
            *(float4*)(a+4) = *(const float4*)(&As[kk][ty*8+4]);
            *(float4*)(w)   = *(const float4*)(&Bs[kk][tx*8]);
            *(float4*)(w+4) = *(const float4*)(&Bs[kk][tx*8+4]);
            #pragma unroll
            for (int i = 0; i < 8; ++i)
                #pragma unroll
                for (int j = 0; j < 8; ++j) acc[i][j] = fmaf(a[i], w[j], acc[i][j]);
        }
        __syncthreads();
    }
    #pragma unroll
    for (int j = 0; j < 8; ++j) {
        float4 v0 = make_float4(acc[0][j], acc[1][j], acc[2][j], acc[3][j]);
        float4 v1 = make_float4(acc[4][j], acc[5][j], acc[6][j], acc[7][j]);
        float* dst = g_encKT + (size_t)(b*512 + e0 + tx*8 + j)*512 + s0 + ty*8;
        *(float4*)dst = v0; *(float4*)(dst+4) = v1;
    }
}

__global__ void init_kernel() {
    int t = threadIdx.x;   // 64
    g_tok[t] = SOS_TOK;
    g_finished[t] = 0;
    g_scores[t] = 0.f;
}

// ---------------- kernel 1: q = e @ Wq  (reads Wq exactly once total) ----------------
// grid 64 (8 cols each), 256 threads: thread = (row r = t>>2, col pair (t&3)*2).
__global__ void __launch_bounds__(256) q_kernel(const float* __restrict__ emb,
                                                const float* __restrict__ Wq) {
    __shared__ float e_s[64][65];   // [dd][row]
    __shared__ float w_s[64][8];    // [dd][col]
    __shared__ int   toks[64];
    int t = threadIdx.x;
    int c0 = blockIdx.x * 8;
    int r = t >> 2;
    int cp = (t & 3) * 2;
    if (t < 64) toks[t] = g_tok[t];
    __syncthreads();
    float acc0 = 0.f, acc1 = 0.f;
    for (int d0 = 0; d0 < 512; d0 += 64) {
        #pragma unroll
        for (int i = 0; i < 16; ++i) {
            int idx = t + i*256;
            int r2 = idx >> 6, dd = idx & 63;
            e_s[dd][r2] = emb[(size_t)toks[r2]*512 + d0 + dd];
        }
        #pragma unroll
        for (int i = 0; i < 2; ++i) {
            int idx = t*2 + i;
            int dd = idx >> 3, cc = idx & 7;
            w_s[dd][cc] = Wq[(size_t)(d0+dd)*512 + c0 + cc];
        }
        __syncthreads();
        #pragma unroll 16
        for (int dd = 0; dd < 64; ++dd) {
            float ev = e_s[dd][r];
            acc0 = fmaf(ev, w_s[dd][cp],   acc0);
            acc1 = fmaf(ev, w_s[dd][cp+1], acc1);
        }
        __syncthreads();
    }
    g_q[r*512 + c0 + cp]     = acc0;
    g_q[r*512 + c0 + cp + 1] = acc1;
}

// ---------------- kernel 2: attention, one block per (b,k) ----------------
__global__ void __launch_bounds__(512) att_kernel(const float* __restrict__ enc,
                                                  const int* __restrict__ lens,
                                                  const float* __restrict__ emb) {
    int row = blockIdx.x;          // 64
    int b = row >> 2;
    int t = threadIdx.x;           // 512
    int wid = t >> 5, lane = t & 31;
    __shared__ float q_s[DD];
    __shared__ float p_s[SS];
    __shared__ float red[16], red2[16];

    float e_t = emb[(size_t)g_tok[row]*DD + t];
    q_s[t] = g_q[row*DD + t];
    __syncthreads();

    // attention score at position t
    int len = lens[b];
    const float scale = 0.044194173824159216f;
    float sc;
    if (t < len) {
        const float* kp = g_encKT + (size_t)b*DD*SS + t;
        float a0=0.f, a1=0.f, a2=0.f, a3=0.f;
        for (int e0 = 0; e0 < DD; e0 += 16) {
            #pragma unroll
            for (int j = 0; j < 16; j += 4) {
                a0 = fmaf(q_s[e0+j+0], kp[(size_t)(e0+j+0)*SS], a0);
                a1 = fmaf(q_s[e0+j+1], kp[(size_t)(e0+j+1)*SS], a1);
                a2 = fmaf(q_s[e0+j+2], kp[(size_t)(e0+j+2)*SS], a2);
                a3 = fmaf(q_s[e0+j+3], kp[(size_t)(e0+j+3)*SS], a3);
            }
        }
        sc = ((a0+a1)+(a2+a3)) * scale;
    } else sc = NEGV;

    // softmax: warp-shuffle reductions, 2 barriers
    float m = sc;
    #pragma unroll
    for (int off = 16; off > 0; off >>= 1) m = fmaxf(m, __shfl_xor_sync(0xffffffffu, m, off));
    if (lane == 0) red[wid] = m;
    __syncthreads();
    float mm = red[0];
    #pragma unroll
    for (int i = 1; i < 16; ++i) mm = fmaxf(mm, red[i]);
    float ex = expf(sc - mm);
    p_s[t] = ex;
    float ss = ex;
    #pragma unroll
    for (int off = 16; off > 0; off >>= 1) ss += __shfl_xor_sync(0xffffffffu, ss, off);
    if (lane == 0) red2[wid] = ss;
    __syncthreads();
    float tot = red2[0];
    #pragma unroll
    for (int i = 1; i < 16; ++i) tot += red2[i];
    float inv = 1.f / tot;

    // ctx[t] = sum_s p[s] * enc[b][s][t]
    {
        const float* ep = enc + (size_t)b*SS*DD + t;
        float a0=0.f, a1=0.f, a2=0.f, a3=0.f;
        for (int s0 = 0; s0 < SS; s0 += 16) {
            #pragma unroll
            for (int j = 0; j < 16; j += 4) {
                a0 = fmaf(p_s[s0+j+0], ep[(size_t)(s0+j+0)*DD], a0);
                a1 = fmaf(p_s[s0+j+1], ep[(size_t)(s0+j+1)*DD], a1);
                a2 = fmaf(p_s[s0+j+2], ep[(size_t)(s0+j+2)*DD], a2);
                a3 = fmaf(p_s[s0+j+3], ep[(size_t)(s0+j+3)*DD], a3);
            }
        }
        g_hT[t*NR + row] = e_t + ((a0+a1)+(a2+a3))*inv;
    }
}

// ---------------- kernel 3: logits GEMM (f32x2) + fused per-block reduction ----------------
// grid 500 (rg = bx&3 -> 16 rows, cg = bx>>2 -> 256 cols), 256 threads, 32KB static smem.
__global__ void __launch_bounds__(256) logits_kernel(const float* __restrict__ Wfc,
                                                     const float* __restrict__ bfc) {
    __shared__ float h_s[DD*16];           // [d][16 rows] = 32 KB
    int rg = blockIdx.x & 3;
    int cg = blockIdx.x >> 2;
    int t = threadIdx.x;

    for (int i = t; i < DD*16; i += 256) {
        int d = i >> 4, r = i & 15;
        h_s[i] = g_hT[d*NR + rg*16 + r];
    }
    __syncthreads();

    int v = cg*256 + t;
    float bias = bfc[v];
    unsigned long long acc[8];
    unsigned long long bias2; PACK2(bias2, bias, bias);
    #pragma unroll
    for (int j = 0; j < 8; ++j) acc[j] = bias2;

    for (int d0 = 0; d0 < DD; d0 += 8) {
        float w[8];
        #pragma unroll
        for (int j = 0; j < 8; ++j) w[j] = Wfc[(size_t)(d0+j)*VV + v];
        #pragma unroll
        for (int j = 0; j < 8; ++j) {
            unsigned long long w2; PACK2(w2, w[j], w[j]);
            const ulonglong2* hp = (const ulonglong2*)(h_s + (d0+j)*16);
            ulonglong2 p0 = hp[0], p1 = hp[1], p2 = hp[2], p3 = hp[3];
            FMA2(acc[0], p0.x, w2); FMA2(acc[1], p0.y, w2);
            FMA2(acc[2], p1.x, w2); FMA2(acc[3], p1.y, w2);
            FMA2(acc[4], p2.x, w2); FMA2(acc[5], p2.y, w2);
            FMA2(acc[6], p3.x, w2); FMA2(acc[7], p3.y, w2);
        }
    }

    float vals[16];
    #pragma unroll
    for (int j = 0; j < 8; ++j) { float lo, hi; UNPACK2(lo, hi, acc[j]); vals[2*j] = lo; vals[2*j+1] = hi; }

    __syncthreads();                        // done reading h tile; reuse smem
    float* sv = h_s;                        // [16][257]
    #pragma unroll
    for (int r = 0; r < 16; ++r) sv[r*257 + t] = vals[r];
    __syncthreads();

    // warp w reduces rows 2w, 2w+1 over this block's 256 columns
    int w = t >> 5, l = t & 31;
    #pragma unroll
    for (int rr = 0; rr < 2; ++rr) {
        int r = w*2 + rr;
        float x[8]; int xi[8];
        #pragma unroll
        for (int i = 0; i < 8; ++i) { x[i] = sv[r*257 + l + 32*i]; xi[i] = cg*256 + l + 32*i; }
        float m = x[0];
        #pragma unroll
        for (int i = 1; i < 8; ++i) m = fmaxf(m, x[i]);
        #pragma unroll
        for (int off = 16; off > 0; off >>= 1) m = fmaxf(m, __shfl_xor_sync(0xffffffffu, m, off));
        float s = 0.f;
        #pragma unroll
        for (int i = 0; i < 8; ++i) s += expf(x[i] - m);
        #pragma unroll
        for (int off = 16; off > 0; off >>= 1) s += __shfl_xor_sync(0xffffffffu, s, off);
        float tv[4] = {-3.4e38f, -3.4e38f, -3.4e38f, -3.4e38f};
        int   ti[4] = {0x7fffffff, 0x7fffffff, 0x7fffffff, 0x7fffffff};
        #pragma unroll
        for (int i = 0; i < 8; ++i) insert4(tv, ti, x[i], xi[i]);
        #pragma unroll
        for (int off = 16; off > 0; off >>= 1) {
            float bv[4]; int bi[4];
            #pragma unroll
            for (int j = 0; j < 4; ++j) {
                bv[j] = __shfl_xor_sync(0xffffffffu, tv[j], off);
                bi[j] = __shfl_xor_sync(0xffffffffu, ti[j], off);
            }
            merge4(tv, ti, bv, bi);
        }
        if (l == 0) {
            int grow = rg*16 + r;
            int p = grow*NCG + cg;
            g_pmax[p] = m;
            g_psum[p] = s;
            #pragma unroll
            for (int j = 0; j < 4; ++j) { g_pval[p*4+j] = tv[j]; g_pidx[p*4+j] = ti[j]; }
        }
    }
}

// ---------------- kernel 4: merge partials + beam combine ----------------
__global__ void __launch_bounds__(128) combine_kernel(int tstep) {
    int b = blockIdx.x;
    int t = threadIdx.x;
    int w = t >> 5, l = t & 31;
    __shared__ float s_lse[KK];
    __shared__ float s_tv[KK][KK];
    __shared__ int   s_ti[KK][KK];
    __shared__ int   nbeam[KK], ntok[KK], nfin[KK];
    __shared__ float nsc[KK];
    __shared__ int   oldseq[KK][TT];
    __shared__ int   oldfin[KK];
    __shared__ float oldsc[KK];

    {
        int row = b*KK + w;
        float m = -3.4e38f, s = 0.f;
        float tv[4] = {-3.4e38f, -3.4e38f, -3.4e38f, -3.4e38f};
        int   ti[4] = {0x7fffffff, 0x7fffffff, 0x7fffffff, 0x7fffffff};
        for (int c = l; c < NCG; c += 32) {
            int p = row*NCG + c;
            float pm = g_pmax[p], ps = g_psum[p];
            float M = fmaxf(m, pm);
            s = s*expf(m - M) + ps*expf(pm - M);
            m = M;
            float bv[4]; int bi[4];
            #pragma unroll
            for (int j = 0; j < 4; ++j) { bv[j] = g_pval[p*4+j]; bi[j] = g_pidx[p*4+j]; }
            merge4(tv, ti, bv, bi);
        }
        #pragma unroll
        for (int off = 16; off > 0; off >>= 1) {
            float pm = __shfl_xor_sync(0xffffffffu, m, off);
            float ps = __shfl_xor_sync(0xffffffffu, s, off);
            float M = fmaxf(m, pm);
            s = s*expf(m - M) + ps*expf(pm - M);
            m = M;
            float bv[4]; int bi[4];
            #pragma unroll
            for (int j = 0; j < 4; ++j) {
                bv[j] = __shfl_xor_sync(0xffffffffu, tv[j], off);
                bi[j] = __shfl_xor_sync(0xffffffffu, ti[j], off);
            }
            merge4(tv, ti, bv, bi);
        }
        if (l == 0) {
            s_lse[w] = m + logf(s);
            #pragma unroll
            for (int j = 0; j < 4; ++j) { s_tv[w][j] = tv[j]; s_ti[w][j] = ti[j]; }
        }
    }

    if (t < KK) { oldfin[t] = g_finished[b*KK + t]; oldsc[t] = g_scores[b*KK + t]; }
    for (int i = t; i < KK*TT; i += 128) oldseq[i >> 6][i & 63] = g_seqs[b*KK*TT + i];
    __syncthreads();

    if (tstep == 1) {
        if (t < KK) {
            int tok = s_ti[0][t];
            g_scores[b*KK + t]   = s_tv[0][t] - s_lse[0];
            g_tok[b*KK + t]      = tok;
            g_finished[b*KK + t] = (tok == EOS_TOK) ? 1 : 0;
        }
        for (int i = t; i < KK*TT; i += 128) {
            int k = i >> 6, j = i & 63;
            int v = (j == 0) ? SOS_TOK : (j == 1 ? s_ti[0][k] : PAD_TOK);
            g_seqs[b*KK*TT + i] = v;
        }
        return;
    }

    if (t == 0) {
        float cl[KK*KK]; int cv[KK*KK];
        for (int k = 0; k < KK; ++k) {
            if (oldfin[k]) {
                cl[k*KK+0] = 0.f; cv[k*KK+0] = PAD_TOK;
                for (int j = 1; j < KK; ++j) { cl[k*KK+j] = NEGV; cv[k*KK+j] = PAD_TOK; }
            } else {
                for (int j = 0; j < KK; ++j) {
                    cl[k*KK+j] = s_tv[k][j] - s_lse[k];
                    cv[k*KK+j] = s_ti[k][j];
                }
            }
        }
        float total[KK*KK];
        for (int i = 0; i < KK*KK; ++i) total[i] = oldsc[i >> 2] + cl[i];
        bool used[KK*KK] = {false};
        for (int k = 0; k < KK; ++k) {
            int best = -1;
            for (int i = 0; i < KK*KK; ++i)
                if (!used[i] && (best < 0 || total[i] > total[best])) best = i;
            used[best] = true;
            int beam = best >> 2;
            nbeam[k] = beam;
            ntok[k]  = cv[best];
            nsc[k]   = total[best];
            nfin[k]  = oldfin[beam] | (cv[best] == EOS_TOK ? 1 : 0);
        }
    }
    __syncthreads();

    if (t < KK) {
        g_scores[b*KK + t]   = nsc[t];
        g_finished[b*KK + t] = nfin[t];
        g_tok[b*KK + t]      = ntok[t];
    }
    for (int i = t; i < KK*TT; i += 128) {
        int k = i >> 6, j = i & 63;
        g_seqs[b*KK*TT + i] = (j == tstep) ? ntok[k] : oldseq[nbeam[k]][j];
    }
}

// ---------------- kernel 5: output ----------------
__global__ void out_kernel(float* __restrict__ out, int out_size) {
    int b = blockIdx.x;     // 16
    int t = threadIdx.x;    // 64
    __shared__ int best;
    __shared__ float bestsc;
    if (t == 0) {
        int bi = 0; float bs = g_scores[b*KK];
        for (int k = 1; k < KK; ++k)
            if (g_scores[b*KK + k] > bs) { bs = g_scores[b*KK + k]; bi = k; }
        best = bi; bestsc = bs;
    }
    __syncthreads();
    if (out_size >= BB*TT + BB) {
        out[b*TT + t] = (float)g_seqs[b*KK*TT + best*TT + t];
        if (t == 0) out[BB*TT + b] = bestsc;
    } else if (out_size == BB*TT) {
        out[b*TT + t] = (float)g_seqs[b*KK*TT + best*TT + t];
    } else if (out_size == BB) {
        if (t == 0) out[b] = bestsc;
    }
}

// ---------------- launcher ----------------
extern "C" void kernel_launch(void* const* d_in, const int* in_sizes, int n_in,
                              void* d_out, int out_size) {
    const float* enc  = (const float*)d_in[0];
    const int*   lens = (const int*)  d_in[1];
    const float* emb  = (const float*)d_in[2];
    const float* Wq   = (const float*)d_in[3];
    const float* Wk   = (const float*)d_in[4];
    const float* Wfc  = (const float*)d_in[5];
    const float* bfc  = (const float*)d_in[6];

    enck_kernel<<<dim3(4, 64), 256>>>(enc, Wk);
    init_kernel<<<1, 64>>>();

    for (int step = 1; step < TT; ++step) {
        q_kernel<<<64, 256>>>(emb, Wq);
        att_kernel<<<NR, 512>>>(enc, lens, emb);
        logits_kernel<<<4*NCG, 256>>>(Wfc, bfc);
        combine_kernel<<<BB, 128>>>(step);
    }

    out_kernel<<<BB, 64>>>((float*)d_out, out_size);
}

// round 5
// speedup vs baseline: 1.5285x; 1.5285x over previous
#include <cuda_runtime.h>
#include <math.h>

#define BB 16
#define SS 512
#define DD 512
#define VV 32000
#define KK 4
#define TT 64
#define NR (BB*KK)     // 64 rows
#define NCG (VV/256)   // 125 vocab col-groups of 256
#define SOS_TOK 1
#define EOS_TOK 2
#define PAD_TOK 0
#define NEGV (-1e9f)

// ---------------- device state ----------------
__device__ float g_encK[BB*SS*DD];     // [b][s][d]  (16.8 MB)
__device__ float g_embQ[VV*DD];        // emb @ Wq   (65.5 MB)
__device__ float g_hT[DD*NR];          // [d][row]
__device__ float g_pmax[NR*NCG];
__device__ float g_psum[NR*NCG];
__device__ float g_pval[NR*NCG*4];
__device__ int   g_pidx[NR*NCG*4];
__device__ int   g_tok[NR];
__device__ float g_scores[NR];
__device__ int   g_finished[NR];
__device__ int   g_seqs[BB*KK*TT];

__device__ __forceinline__ bool better(float xv, int xi, float yv, int yi) {
    return (xv > yv) || (xv == yv && xi < yi);
}

#define FMA2(acc,a,b) asm("fma.rn.f32x2 %0, %1, %2, %3;" : "=l"(acc) : "l"(a), "l"(b), "l"(acc))
#define PACK2(d,x,y)  asm("mov.b64 %0, {%1, %2};" : "=l"(d) : "f"(x), "f"(y))
#define UNPACK2(x,y,d) asm("mov.b64 {%0, %1}, %2;" : "=f"(x), "=f"(y) : "l"(d))

__device__ __forceinline__ void merge4(float av[4], int ai[4], const float bv[4], const int bi[4]) {
    float ov[4]; int oi[4]; int i = 0, j = 0;
    #pragma unroll
    for (int o = 0; o < 4; ++o) {
        bool ta = (j >= 4) || (i < 4 && better(av[i], ai[i], bv[j], bi[j]));
        if (ta) { ov[o] = av[i]; oi[o] = ai[i]; ++i; }
        else    { ov[o] = bv[j]; oi[o] = bi[j]; ++j; }
    }
    #pragma unroll
    for (int o = 0; o < 4; ++o) { av[o] = ov[o]; ai[o] = oi[o]; }
}

__device__ __forceinline__ void insert4(float av[4], int ai[4], float x, int xi) {
    if (better(x, xi, av[3], ai[3])) {
        if (better(x, xi, av[0], ai[0]))      { av[3]=av[2];ai[3]=ai[2]; av[2]=av[1];ai[2]=ai[1]; av[1]=av[0];ai[1]=ai[0]; av[0]=x;ai[0]=xi; }
        else if (better(x, xi, av[1], ai[1])) { av[3]=av[2];ai[3]=ai[2]; av[2]=av[1];ai[2]=ai[1]; av[1]=x;ai[1]=xi; }
        else if (better(x, xi, av[2], ai[2])) { av[3]=av[2];ai[3]=ai[2]; av[2]=x;ai[2]=xi; }
        else                                  { av[3]=x;ai[3]=xi; }
    }
}

// ---------------- generic 128x128 tile SGEMM (K=512, N=512), f32x2 inner ----------------
// C = A[M,512] @ B[512,512], row-major. which: 0 -> g_encK, 1 -> g_embQ.
__global__ void __launch_bounds__(256) gemm_kernel(const float* __restrict__ A,
                                                   const float* __restrict__ B,
                                                   int which) {
    float* C = which ? g_embQ : g_encK;
    __shared__ float As[32][132];   // [k][m]
    __shared__ float Bs[32][132];   // [k][n]
    int n0 = blockIdx.x * 128;
    int m0 = blockIdx.y * 128;
    int t = threadIdx.x;
    int tx = t & 15, ty = t >> 4;
    unsigned long long acc2[8][4];
    #pragma unroll
    for (int i = 0; i < 8; ++i)
        #pragma unroll
        for (int j = 0; j < 4; ++j) acc2[i][j] = 0ull;

    for (int k0 = 0; k0 < 512; k0 += 32) {
        #pragma unroll
        for (int i = 0; i < 4; ++i) {
            int idx = t + i*256;
            int mi = idx >> 3, kq = idx & 7;
            float4 f = *(const float4*)(A + (size_t)(m0 + mi)*512 + k0 + kq*4);
            As[kq*4+0][mi] = f.x; As[kq*4+1][mi] = f.y; As[kq*4+2][mi] = f.z; As[kq*4+3][mi] = f.w;
        }
        #pragma unroll
        for (int i = 0; i < 4; ++i) {
            int idx = t + i*256;
            int kk = idx >> 5, nq = idx & 31;
            *(float4*)(&Bs[kk][nq*4]) = *(const float4*)(B + (size_t)(k0+kk)*512 + n0 + nq*4);
        }
        __syncthreads();
        #pragma unroll 4
        for (int kk = 0; kk < 32; ++kk) {
            float a[8];
            *(float4*)(a)   = *(const float4*)(&As[kk][ty*8]);
            *(float4*)(a+4) = *(const float4*)(&As[kk][ty*8+4]);
            const unsigned long long* wp = (const unsigned long long*)(&Bs[kk][tx*8]);
            unsigned long long w0 = wp[0], w1 = wp[1], w2 = wp[2], w3 = wp[3];
            #pragma unroll
            for (int i = 0; i < 8; ++i) {
                unsigned long long a2; PACK2(a2, a[i], a[i]);
                FMA2(acc2[i][0], a2, w0);
                FMA2(acc2[i][1], a2, w1);
                FMA2(acc2[i][2], a2, w2);
                FMA2(acc2[i][3], a2, w3);
            }
        }
        __syncthreads();
    }
    #pragma unroll
    for (int i = 0; i < 8; ++i) {
        float o[8];
        #pragma unroll
        for (int j = 0; j < 4; ++j) { UNPACK2(o[2*j], o[2*j+1], acc2[i][j]); }
        float* dst = C + (size_t)(m0 + ty*8 + i)*512 + n0 + tx*8;
        *(float4*)dst = *(float4*)(o);
        *(float4*)(dst+4) = *(float4*)(o+4);
    }
}

__global__ void init_kernel() {
    int t = threadIdx.x;   // 64
    g_tok[t] = SOS_TOK;
    g_finished[t] = 0;
    g_scores[t] = 0.f;
}

// ---------------- attention: one block per (b,k), warp-per-s scores ----------------
__global__ void __launch_bounds__(512, 1) att_kernel(const float* __restrict__ enc,
                                                     const int* __restrict__ lens,
                                                     const float* __restrict__ emb) {
    int row = blockIdx.x;          // 64
    int b = row >> 2;
    int t = threadIdx.x;           // 512
    int wid = t >> 5, lane = t & 31;
    __shared__ float q_s[DD];
    __shared__ float p_s[SS];
    __shared__ float red[16], red2[16];

    int tok = g_tok[row];
    q_s[t] = g_embQ[(size_t)tok*DD + t];
    float e_t = emb[(size_t)tok*DD + t];
    int len = lens[b];
    __syncthreads();

    // scores: warp wid computes s = wid*32 .. wid*32+31, two at a time (32 indep coalesced loads)
    const float scale = 0.044194173824159216f;  // 1/sqrt(512)
    const float* kb = g_encK + (size_t)b*SS*DD;
    #pragma unroll 2
    for (int i = 0; i < 32; i += 2) {
        int s0 = wid*32 + i;
        const float* k0 = kb + (size_t)s0*DD + lane;
        const float* k1 = k0 + DD;
        float a0 = 0.f, a1 = 0.f;
        #pragma unroll
        for (int j = 0; j < 16; ++j) {
            float qv = q_s[lane + 32*j];
            a0 = fmaf(qv, k0[32*j], a0);
            a1 = fmaf(qv, k1[32*j], a1);
        }
        #pragma unroll
        for (int off = 16; off > 0; off >>= 1) {
            a0 += __shfl_xor_sync(0xffffffffu, a0, off);
            a1 += __shfl_xor_sync(0xffffffffu, a1, off);
        }
        if (lane == 0) {
            p_s[s0]     = (s0     < len) ? a0*scale : NEGV;
            p_s[s0 + 1] = (s0 + 1 < len) ? a1*scale : NEGV;
        }
    }
    __syncthreads();

    // softmax
    float sc = p_s[t];
    float m = sc;
    #pragma unroll
    for (int off = 16; off > 0; off >>= 1) m = fmaxf(m, __shfl_xor_sync(0xffffffffu, m, off));
    if (lane == 0) red[wid] = m;
    __syncthreads();
    float mm = red[0];
    #pragma unroll
    for (int i = 1; i < 16; ++i) mm = fmaxf(mm, red[i]);
    float ex = expf(sc - mm);
    p_s[t] = ex;
    float ssum = ex;
    #pragma unroll
    for (int off = 16; off > 0; off >>= 1) ssum += __shfl_xor_sync(0xffffffffu, ssum, off);
    if (lane == 0) red2[wid] = ssum;
    __syncthreads();
    float tot = red2[0];
    #pragma unroll
    for (int i = 1; i < 16; ++i) tot += red2[i];
    float inv = 1.f / tot;

    // ctx[t] = sum_s p[s] * enc[b][s][t], 16-deep explicit load batches
    {
        const float* ep = enc + (size_t)b*SS*DD + t;
        float acc = 0.f;
        for (int s0 = 0; s0 < SS; s0 += 16) {
            float v[16];
            #pragma unroll
            for (int j = 0; j < 16; ++j) v[j] = ep[(size_t)(s0+j)*DD];
            #pragma unroll
            for (int j = 0; j < 16; ++j) acc = fmaf(p_s[s0+j], v[j], acc);
        }
        g_hT[t*NR + row] = e_t + acc*inv;
    }
}

// ---------------- logits GEMM (f32x2) + fused per-block reduction ----------------
__global__ void __launch_bounds__(256) logits_kernel(const float* __restrict__ Wfc,
                                                     const float* __restrict__ bfc) {
    __shared__ float h_s[DD*16];           // [d][16 rows] = 32 KB
    int rg = blockIdx.x & 3;
    int cg = blockIdx.x >> 2;
    int t = threadIdx.x;

    for (int i = t; i < DD*16; i += 256) {
        int d = i >> 4, r = i & 15;
        h_s[i] = g_hT[d*NR + rg*16 + r];
    }
    __syncthreads();

    int v = cg*256 + t;
    float bias = bfc[v];
    unsigned long long acc[8];
    unsigned long long bias2; PACK2(bias2, bias, bias);
    #pragma unroll
    for (int j = 0; j < 8; ++j) acc[j] = bias2;

    for (int d0 = 0; d0 < DD; d0 += 8) {
        float w[8];
        #pragma unroll
        for (int j = 0; j < 8; ++j) w[j] = Wfc[(size_t)(d0+j)*VV + v];
        #pragma unroll
        for (int j = 0; j < 8; ++j) {
            unsigned long long w2; PACK2(w2, w[j], w[j]);
            const ulonglong2* hp = (const ulonglong2*)(h_s + (d0+j)*16);
            ulonglong2 p0 = hp[0], p1 = hp[1], p2 = hp[2], p3 = hp[3];
            FMA2(acc[0], p0.x, w2); FMA2(acc[1], p0.y, w2);
            FMA2(acc[2], p1.x, w2); FMA2(acc[3], p1.y, w2);
            FMA2(acc[4], p2.x, w2); FMA2(acc[5], p2.y, w2);
            FMA2(acc[6], p3.x, w2); FMA2(acc[7], p3.y, w2);
        }
    }

    float vals[16];
    #pragma unroll
    for (int j = 0; j < 8; ++j) { float lo, hi; UNPACK2(lo, hi, acc[j]); vals[2*j] = lo; vals[2*j+1] = hi; }

    __syncthreads();
    float* sv = h_s;                        // [16][257]
    #pragma unroll
    for (int r = 0; r < 16; ++r) sv[r*257 + t] = vals[r];
    __syncthreads();

    int w = t >> 5, l = t & 31;
    #pragma unroll
    for (int rr = 0; rr < 2; ++rr) {
        int r = w*2 + rr;
        float x[8]; int xi[8];
        #pragma unroll
        for (int i = 0; i < 8; ++i) { x[i] = sv[r*257 + l + 32*i]; xi[i] = cg*256 + l + 32*i; }
        float m = x[0];
        #pragma unroll
        for (int i = 1; i < 8; ++i) m = fmaxf(m, x[i]);
        #pragma unroll
        for (int off = 16; off > 0; off >>= 1) m = fmaxf(m, __shfl_xor_sync(0xffffffffu, m, off));
        float s = 0.f;
        #pragma unroll
        for (int i = 0; i < 8; ++i) s += expf(x[i] - m);
        #pragma unroll
        for (int off = 16; off > 0; off >>= 1) s += __shfl_xor_sync(0xffffffffu, s, off);
        float tv[4] = {-3.4e38f, -3.4e38f, -3.4e38f, -3.4e38f};
        int   ti[4] = {0x7fffffff, 0x7fffffff, 0x7fffffff, 0x7fffffff};
        #pragma unroll
        for (int i = 0; i < 8; ++i) insert4(tv, ti, x[i], xi[i]);
        #pragma unroll
        for (int off = 16; off > 0; off >>= 1) {
            float bv[4]; int bi[4];
            #pragma unroll
            for (int j = 0; j < 4; ++j) {
                bv[j] = __shfl_xor_sync(0xffffffffu, tv[j], off);
                bi[j] = __shfl_xor_sync(0xffffffffu, ti[j], off);
            }
            merge4(tv, ti, bv, bi);
        }
        if (l == 0) {
            int grow = rg*16 + r;
            int p = grow*NCG + cg;
            g_pmax[p] = m;
            g_psum[p] = s;
            #pragma unroll
            for (int j = 0; j < 4; ++j) { g_pval[p*4+j] = tv[j]; g_pidx[p*4+j] = ti[j]; }
        }
    }
}

// ---------------- merge partials + beam combine ----------------
__global__ void __launch_bounds__(128) combine_kernel(int tstep) {
    int b = blockIdx.x;
    int t = threadIdx.x;
    int w = t >> 5, l = t & 31;
    __shared__ float s_lse[KK];
    __shared__ float s_tv[KK][KK];
    __shared__ int   s_ti[KK][KK];
    __shared__ int   nbeam[KK], ntok[KK], nfin[KK];
    __shared__ float nsc[KK];
    __shared__ int   oldseq[KK][TT];
    __shared__ int   oldfin[KK];
    __shared__ float oldsc[KK];

    {
        int row = b*KK + w;
        float m = -3.4e38f, s = 0.f;
        float tv[4] = {-3.4e38f, -3.4e38f, -3.4e38f, -3.4e38f};
        int   ti[4] = {0x7fffffff, 0x7fffffff, 0x7fffffff, 0x7fffffff};
        for (int c = l; c < NCG; c += 32) {
            int p = row*NCG + c;
            float pm = g_pmax[p], ps = g_psum[p];
            float M = fmaxf(m, pm);
            s = s*expf(m - M) + ps*expf(pm - M);
            m = M;
            float bv[4]; int bi[4];
            #pragma unroll
            for (int j = 0; j < 4; ++j) { bv[j] = g_pval[p*4+j]; bi[j] = g_pidx[p*4+j]; }
            merge4(tv, ti, bv, bi);
        }
        #pragma unroll
        for (int off = 16; off > 0; off >>= 1) {
            float pm = __shfl_xor_sync(0xffffffffu, m, off);
            float ps = __shfl_xor_sync(0xffffffffu, s, off);
            float M = fmaxf(m, pm);
            s = s*expf(m - M) + ps*expf(pm - M);
            m = M;
            float bv[4]; int bi[4];
            #pragma unroll
            for (int j = 0; j < 4; ++j) {
                bv[j] = __shfl_xor_sync(0xffffffffu, tv[j], off);
                bi[j] = __shfl_xor_sync(0xffffffffu, ti[j], off);
            }
            merge4(tv, ti, bv, bi);
        }
        if (l == 0) {
            s_lse[w] = m + logf(s);
            #pragma unroll
            for (int j = 0; j < 4; ++j) { s_tv[w][j] = tv[j]; s_ti[w][j] = ti[j]; }
        }
    }

    if (t < KK) { oldfin[t] = g_finished[b*KK + t]; oldsc[t] = g_scores[b*KK + t]; }
    for (int i = t; i < KK*TT; i += 128) oldseq[i >> 6][i & 63] = g_seqs[b*KK*TT + i];
    __syncthreads();

    if (tstep == 1) {
        if (t < KK) {
            int tok = s_ti[0][t];
            g_scores[b*KK + t]   = s_tv[0][t] - s_lse[0];
            g_tok[b*KK + t]      = tok;
            g_finished[b*KK + t] = (tok == EOS_TOK) ? 1 : 0;
        }
        for (int i = t; i < KK*TT; i += 128) {
            int k = i >> 6, j = i & 63;
            int v = (j == 0) ? SOS_TOK : (j == 1 ? s_ti[0][k] : PAD_TOK);
            g_seqs[b*KK*TT + i] = v;
        }
        return;
    }

    if (t == 0) {
        float cl[KK*KK]; int cv[KK*KK];
        for (int k = 0; k < KK; ++k) {
            if (oldfin[k]) {
                cl[k*KK+0] = 0.f; cv[k*KK+0] = PAD_TOK;
                for (int j = 1; j < KK; ++j) { cl[k*KK+j] = NEGV; cv[k*KK+j] = PAD_TOK; }
            } else {
                for (int j = 0; j < KK; ++j) {
                    cl[k*KK+j] = s_tv[k][j] - s_lse[k];
                    cv[k*KK+j] = s_ti[k][j];
                }
            }
        }
        float total[KK*KK];
        for (int i = 0; i < KK*KK; ++i) total[i] = oldsc[i >> 2] + cl[i];
        bool used[KK*KK] = {false};
        for (int k = 0; k < KK; ++k) {
            int best = -1;
            for (int i = 0; i < KK*KK; ++i)
                if (!used[i] && (best < 0 || total[i] > total[best])) best = i;
            used[best] = true;
            int beam = best >> 2;
            nbeam[k] = beam;
            ntok[k]  = cv[best];
            nsc[k]   = total[best];
            nfin[k]  = oldfin[beam] | (cv[best] == EOS_TOK ? 1 : 0);
        }
    }
    __syncthreads();

    if (t < KK) {
        g_scores[b*KK + t]   = nsc[t];
        g_finished[b*KK + t] = nfin[t];
        g_tok[b*KK + t]      = ntok[t];
    }
    for (int i = t; i < KK*TT; i += 128) {
        int k = i >> 6, j = i & 63;
        g_seqs[b*KK*TT + i] = (j == tstep) ? ntok[k] : oldseq[nbeam[k]][j];
    }
}

// ---------------- output ----------------
__global__ void out_kernel(float* __restrict__ out, int out_size) {
    int b = blockIdx.x;     // 16
    int t = threadIdx.x;    // 64
    __shared__ int best;
    __shared__ float bestsc;
    if (t == 0) {
        int bi = 0; float bs = g_scores[b*KK];
        for (int k = 1; k < KK; ++k)
            if (g_scores[b*KK + k] > bs) { bs = g_scores[b*KK + k]; bi = k; }
        best = bi; bestsc = bs;
    }
    __syncthreads();
    if (out_size >= BB*TT + BB) {
        out[b*TT + t] = (float)g_seqs[b*KK*TT + best*TT + t];
        if (t == 0) out[BB*TT + b] = bestsc;
    } else if (out_size == BB*TT) {
        out[b*TT + t] = (float)g_seqs[b*KK*TT + best*TT + t];
    } else if (out_size == BB) {
        if (t == 0) out[b] = bestsc;
    }
}

// ---------------- launcher ----------------
extern "C" void kernel_launch(void* const* d_in, const int* in_sizes, int n_in,
                              void* d_out, int out_size) {
    const float* enc  = (const float*)d_in[0];
    const int*   lens = (const int*)  d_in[1];
    const float* emb  = (const float*)d_in[2];
    const float* Wq   = (const float*)d_in[3];
    const float* Wk   = (const float*)d_in[4];
    const float* Wfc  = (const float*)d_in[5];
    const float* bfc  = (const float*)d_in[6];

    gemm_kernel<<<dim3(4, 64), 256>>>(enc, Wk, 0);     // encK = enc @ Wk   [b][s][d]
    gemm_kernel<<<dim3(4, 250), 256>>>(emb, Wq, 1);    // embQ = emb @ Wq
    init_kernel<<<1, 64>>>();

    for (int step = 1; step < TT; ++step) {
        att_kernel<<<NR, 512>>>(enc, lens, emb);
        logits_kernel<<<4*NCG, 256>>>(Wfc, bfc);
        combine_kernel<<<BB, 128>>>(step);
    }

    out_kernel<<<BB, 64>>>((float*)d_out, out_size);
}